// round 13
// baseline (speedup 1.0000x reference)
#include <cuda_runtime.h>
#include <cuda_fp16.h>
#include <cstdint>
#include <cstddef>

#define BMAX 32768

__device__ float g_x[BMAX * 64];
__device__ float g_cond[3 * BMAX * 256];
__device__ float g_t[BMAX * 256];
__device__ float g_P[64 * 768];
__device__ float g_pb[768];
__device__ float g_Wsum[256];
__device__ float g_part[BMAX / 4];
__device__ __half g_v16[BMAX * 256];
__device__ __half g_vd16[BMAX * 256];
__device__ __half g_S1[2][256 * 256];   // v@W:   S1[s][n*256+k] = split_s(W[k,n])
__device__ __half g_S2[2][256 * 256];   // a@W^T: S2[s][n*256+k] = split_s(W[n,k])

__host__ __device__ inline uint32_t rotl32(uint32_t v, int d) { return (v << d) | (v >> (32 - d)); }

__host__ __device__ inline void tf2x32(uint32_t k0, uint32_t k1, uint32_t& x0, uint32_t& x1) {
    uint32_t ks2 = k0 ^ k1 ^ 0x1BD11BDAu;
    x0 += k0; x1 += k1;
    x0 += x1; x1 = rotl32(x1, 13); x1 ^= x0;
    x0 += x1; x1 = rotl32(x1, 15); x1 ^= x0;
    x0 += x1; x1 = rotl32(x1, 26); x1 ^= x0;
    x0 += x1; x1 = rotl32(x1,  6); x1 ^= x0;
    x0 += k1;  x1 += ks2 + 1u;
    x0 += x1; x1 = rotl32(x1, 17); x1 ^= x0;
    x0 += x1; x1 = rotl32(x1, 29); x1 ^= x0;
    x0 += x1; x1 = rotl32(x1, 16); x1 ^= x0;
    x0 += x1; x1 = rotl32(x1, 24); x1 ^= x0;
    x0 += ks2; x1 += k0 + 2u;
    x0 += x1; x1 = rotl32(x1, 13); x1 ^= x0;
    x0 += x1; x1 = rotl32(x1, 15); x1 ^= x0;
    x0 += x1; x1 = rotl32(x1, 26); x1 ^= x0;
    x0 += x1; x1 = rotl32(x1,  6); x1 ^= x0;
    x0 += k0;  x1 += k1 + 3u;
    x0 += x1; x1 = rotl32(x1, 17); x1 ^= x0;
    x0 += x1; x1 = rotl32(x1, 29); x1 ^= x0;
    x0 += x1; x1 = rotl32(x1, 16); x1 ^= x0;
    x0 += x1; x1 = rotl32(x1, 24); x1 ^= x0;
    x0 += k1;  x1 += ks2 + 4u;
    x0 += x1; x1 = rotl32(x1, 13); x1 ^= x0;
    x0 += x1; x1 = rotl32(x1, 15); x1 ^= x0;
    x0 += x1; x1 = rotl32(x1, 26); x1 ^= x0;
    x0 += x1; x1 = rotl32(x1,  6); x1 ^= x0;
    x0 += ks2; x1 += k0 + 5u;
}

__device__ inline float tf_uniform(uint32_t k0, uint32_t k1, uint32_t f, uint32_t half_) {
    uint32_t sec = (f >= half_) ? 1u : 0u;
    uint32_t lane = sec ? (f - half_) : f;
    uint32_t x0 = lane, x1 = lane + half_;
    tf2x32(k0, k1, x0, x1);
    uint32_t bits = sec ? x1 : x0;
    return __uint_as_float((bits >> 9) | 0x3f800000u) - 1.0f;
}

__device__ inline void tf_uniform2(uint32_t k0, uint32_t k1, uint32_t f, uint32_t half_,
                                   float& u0, float& u1) {
    uint32_t x0 = f, x1 = f + half_;
    tf2x32(k0, k1, x0, x1);
    u0 = __uint_as_float((x0 >> 9) | 0x3f800000u) - 1.0f;
    u1 = __uint_as_float((x1 >> 9) | 0x3f800000u) - 1.0f;
}

__device__ inline float sigmoidf_(float x) {
    float e = expf(-fabsf(x));
    float s = 1.0f / (1.0f + e);
    return (x >= 0.0f) ? s : (1.0f - s);
}
__device__ inline float softplusf_(float x) {
    return fmaxf(x, 0.0f) + log1pf(expf(-fabsf(x)));
}

// ---------------- smem / mma helpers ----------------
__device__ __forceinline__ uint32_t smem_u32(const void* p) {
    uint32_t a;
    asm("{ .reg .u64 t; cvta.to.shared.u64 t, %1; cvt.u32.u64 %0, t; }" : "=r"(a) : "l"(p));
    return a;
}
#define SWZ(o) ((o) ^ (((o) >> 3) & 0x70))

#define CP16(dst, src) \
    asm volatile("cp.async.cg.shared.global [%0], [%1], 16;" :: "r"(dst), "l"(src))
#define CPC() asm volatile("cp.async.commit_group;" ::: "memory")
template <int N> __device__ __forceinline__ void cp_wait() {
    asm volatile("cp.async.wait_group %0;" :: "n"(N) : "memory");
}

__device__ __forceinline__ void ldm4(uint32_t* r, uint32_t a) {
    asm volatile("ldmatrix.sync.aligned.m8n8.x4.shared.b16 {%0,%1,%2,%3}, [%4];"
        : "=r"(r[0]), "=r"(r[1]), "=r"(r[2]), "=r"(r[3]) : "r"(a));
}
__device__ __forceinline__ void mma16816(float* d, const uint32_t* a, const uint32_t* b) {
    asm volatile(
        "mma.sync.aligned.m16n8k16.row.col.f32.f16.f16.f32 "
        "{%0,%1,%2,%3}, {%4,%5,%6,%7}, {%8,%9}, {%0,%1,%2,%3};"
        : "+f"(d[0]), "+f"(d[1]), "+f"(d[2]), "+f"(d[3])
        : "r"(a[0]), "r"(a[1]), "r"(a[2]), "r"(a[3]), "r"(b[0]), "r"(b[1]));
}

__device__ __forceinline__ uint32_t pkh(float x, float y) {
    __half2 h = __floats2half2_rn(x, y);
    return *(uint32_t*)&h;
}
__device__ __forceinline__ void split2(float a, float& hi, float& lo) {
    hi = __half2float(__float2half_rn(a));
    lo = a - hi;
}

// ---------------- prep ----------------
__global__ void __launch_bounds__(256) prep_kernel(
    const float* __restrict__ W, const float* __restrict__ b, const float* __restrict__ c,
    const float* __restrict__ fc2w, const float* __restrict__ fc2b)
{
    int idx = blockIdx.x * blockDim.x + threadIdx.x;
    int stride = gridDim.x * blockDim.x;
    for (int i = idx; i < 256 * 256; i += stride) {
        int n = i >> 8, k = i & 255;
        float w1 = W[k * 256 + n];
        float h1, l1; split2(w1, h1, l1);
        g_S1[0][i] = __float2half_rn(h1);
        g_S1[1][i] = __float2half_rn(l1);
        float w2 = W[n * 256 + k];
        float h2, l2; split2(w2, h2, l2);
        g_S2[0][i] = __float2half_rn(h2);
        g_S2[1][i] = __float2half_rn(l2);
    }
    for (int i = idx; i < 64 * 768; i += stride) {
        int k = i / 768, n = i % 768;
        float val;
        if (n < 256)      val = b[n] * fc2w[n * 64 + k] + fc2w[(256 + n) * 64 + k];
        else if (n < 512) { int j = n - 256; val = c[j] * fc2w[(512 + j) * 64 + k] + fc2w[(768 + j) * 64 + k]; }
        else              { int j = n - 512; val = fc2w[(1024 + j) * 64 + k]; }
        g_P[k * 768 + n] = val;
    }
    for (int i = idx; i < 768; i += stride) {
        float val;
        if (i < 256)      val = b[i] * (1.0f + fc2b[i]) + fc2b[256 + i];
        else if (i < 512) { int j = i - 256; val = c[j] * (1.0f + fc2b[512 + j]) + fc2b[768 + j]; }
        else              { int j = i - 512; val = fc2b[1024 + j]; }
        g_pb[i] = val;
    }
    for (int i = idx; i < 256; i += stride) {
        float s = 0.0f;
        for (int rr = 0; rr < 256; rr++) s += W[rr * 256 + i];
        g_Wsum[i] = s;
    }
}

// ---------------- cond fc1 ----------------
__global__ void __launch_bounds__(256) cond_fc1_kernel(
    const float* __restrict__ cond, const float* __restrict__ fc1w,
    const float* __restrict__ fc1b, float* __restrict__ xout)
{
    __shared__ float Cs[64][65];
    __shared__ float Ws[64][65];
    int t = threadIdx.x;
    int r0 = blockIdx.x * 64;
#pragma unroll
    for (int l = 0; l < 4; l++) {
        int id = t + l * 256;
        int j = id >> 4, k4 = (id & 15) << 2;
        float4 w = *(const float4*)(fc1w + j * 64 + k4);
        Ws[k4 + 0][j] = w.x; Ws[k4 + 1][j] = w.y; Ws[k4 + 2][j] = w.z; Ws[k4 + 3][j] = w.w;
    }
#pragma unroll
    for (int l = 0; l < 4; l++) {
        int id = t + l * 256;
        int i = id >> 4, k4 = (id & 15) << 2;
        float4 v = *(const float4*)(cond + (size_t)(r0 + i) * 64 + k4);
        Cs[i][k4 + 0] = v.x; Cs[i][k4 + 1] = v.y; Cs[i][k4 + 2] = v.z; Cs[i][k4 + 3] = v.w;
    }
    __syncthreads();
    int tx = t & 15, ty = t >> 4;
    float acc[4][4];
#pragma unroll
    for (int i = 0; i < 4; i++)
#pragma unroll
        for (int j = 0; j < 4; j++) acc[i][j] = 0.0f;
#pragma unroll 8
    for (int k = 0; k < 64; k++) {
        float a[4], bv[4];
#pragma unroll
        for (int i = 0; i < 4; i++) a[i] = Cs[ty * 4 + i][k];
#pragma unroll
        for (int j = 0; j < 4; j++) bv[j] = Ws[k][tx * 4 + j];
#pragma unroll
        for (int i = 0; i < 4; i++)
#pragma unroll
            for (int j = 0; j < 4; j++) acc[i][j] = fmaf(a[i], bv[j], acc[i][j]);
    }
#pragma unroll
    for (int i = 0; i < 4; i++) {
        int r = r0 + ty * 4 + i;
#pragma unroll
        for (int j = 0; j < 4; j++) {
            int jj = tx * 4 + j;
            xout[(size_t)r * 64 + jj] = tanhf(acc[i][j] + fc1b[jj]);
        }
    }
}

// ---------------- cond-param SGEMM (fp32, K=64, N=768) ----------------
__global__ void __launch_bounds__(256, 2) sgemm0_kernel(
    const float* __restrict__ A, const float* __restrict__ Bm,
    float* __restrict__ out, const float* __restrict__ pb, int M)
{
    __shared__ float As[16][132];
    __shared__ float Bs[16][128];
    const int t = threadIdx.x;
    const int tx = t & 15, ty = t >> 4;
    const int bx = blockIdx.x, by = blockIdx.y;
    const int N = 768, K = 64;
    const float* Ab = A + (size_t)by * 128 * K;
    const float* Bb = Bm + (size_t)bx * 128;
    float acc[8][8];
#pragma unroll
    for (int i = 0; i < 8; i++)
#pragma unroll
        for (int j = 0; j < 8; j++) acc[i][j] = 0.0f;
    for (int kb = 0; kb < K; kb += 16) {
#pragma unroll
        for (int l = 0; l < 2; l++) {
            int id = t + l * 256;
            int row = id >> 2, c4 = (id & 3) << 2;
            float4 va = *(const float4*)(Ab + (size_t)row * K + kb + c4);
            As[c4 + 0][row] = va.x; As[c4 + 1][row] = va.y;
            As[c4 + 2][row] = va.z; As[c4 + 3][row] = va.w;
        }
#pragma unroll
        for (int l = 0; l < 2; l++) {
            int id = t + l * 256;
            int kk = id >> 5, n4 = (id & 31) << 2;
            *(float4*)&Bs[kk][n4] = *(const float4*)(Bb + (size_t)(kb + kk) * N + n4);
        }
        __syncthreads();
#pragma unroll
        for (int kk = 0; kk < 16; kk++) {
            float a[8], bv[8];
#pragma unroll
            for (int i = 0; i < 8; i++) a[i] = As[kk][ty * 8 + i];
#pragma unroll
            for (int j = 0; j < 8; j++) bv[j] = Bs[kk][tx * 8 + j];
#pragma unroll
            for (int i = 0; i < 8; i++)
#pragma unroll
                for (int j = 0; j < 8; j++) acc[i][j] = fmaf(a[i], bv[j], acc[i][j]);
        }
        __syncthreads();
    }
#pragma unroll
    for (int i = 0; i < 8; i++) {
        int r = by * 128 + ty * 8 + i;
#pragma unroll
        for (int j = 0; j < 8; j++) {
            int c = bx * 128 + tx * 8 + j;
            float val = acc[i][j] + pb[c];
            if (c >= 512) val = 1.0f + 0.05f * tanhf(val);
            out[(size_t)(c >> 8) * M * 256 + (size_t)r * 256 + (c & 255)] = val;
        }
    }
}

// ---------------- init: vd16 = fp16(v_data); v16 = noise/copy ----------------
__global__ void __launch_bounds__(256) init_v_kernel(
    const float* __restrict__ vdata, __half* __restrict__ v16,
    __half* __restrict__ vd16, int B, int n_noise, uint32_t k0, uint32_t k1)
{
    int total = B * 256;
    uint32_t half_ = (uint32_t)(n_noise * 128);
    for (int idx = blockIdx.x * blockDim.x + threadIdx.x; idx < total;
         idx += gridDim.x * blockDim.x) {
        int r = idx >> 8;
        float vd = vdata[idx];
        vd16[idx] = __float2half_rn(vd);
        float val = vd;
        if (r < n_noise) {
            float u = tf_uniform(k0, k1, (uint32_t)idx, half_);
            val = (u < 0.5f) ? 1.0f : 0.0f;
        }
        v16[idx] = __float2half_rn(val);
    }
}

// ---------------- fused Gibbs chain: 5 steps, all intermediates in smem ----------------
// smem: VT (v tile, 4 chunks x 16KB) @0; AH @65536; AL @131072; B-staging @196608 (2x16KB)
#define FG_VT 0
#define FG_AH 65536
#define FG_AL 131072
#define FG_BS 196608
#define FG_SMEM 229376

struct GKeys { uint32_t a[20]; };   // per step s: a[4s..4s+3] = k1s0,k1s1,k2s0,k2s1

__global__ void __launch_bounds__(256, 1) fused_gibbs(
    const float* __restrict__ ws, const float* __restrict__ cmod,
    const float* __restrict__ bmod,
    const __half* __restrict__ S1a, const __half* __restrict__ S1b,
    const __half* __restrict__ S2a, const __half* __restrict__ S2b,
    __half* __restrict__ v16, int Bn, GKeys keys, uint32_t hlf)
{
    extern __shared__ char sm[];
    const uint32_t smb = smem_u32(sm);
    const int t = threadIdx.x;
    const int lane = t & 31;
    const int wid = t >> 5;
    const int wm = wid & 1, wn = wid >> 1;
    const int by = blockIdx.x;
    const int Mh = Bn >> 1;

    const int arow = lane & 15;
    const int acolb = (lane >> 4) * 16;
    const int brow = (lane & 7) + (lane >> 4) * 8;
    const int bcolb = ((lane >> 3) & 1) * 16;
    const int g = lane >> 2, t4 = lane & 3;

    // ---- init: stage v16 -> VT (4 chunks) ----
#pragma unroll
    for (int i = 0; i < 16; i++) {
        int u = t + i * 256;
        int kcc = u >> 10, r = (u >> 3) & 127, q = u & 7;
        int gr = (r < 64) ? (by * 64 + r) : (Mh + by * 64 + (r - 64));
        CP16(smb + FG_VT + kcc * 16384 + SWZ(r * 128 + q * 16),
             v16 + (size_t)gr * 256 + kcc * 64 + q * 8);
    }
    CPC(); cp_wait<0>(); __syncthreads();

#pragma unroll 1
    for (int s = 0; s < 5; s++) {
        // ================= mode1: h-sample -> AH/AL =================
        {
            const uint32_t rk0 = keys.a[s * 4 + 0], rk1 = keys.a[s * 4 + 1];
#pragma unroll 1
            for (int np = 0; np < 2; np++) {
                float acc[4][4][4];
#pragma unroll
                for (int j = 0; j < 4; j++)
#pragma unroll
                    for (int n = 0; n < 4; n++)
#pragma unroll
                        for (int q = 0; q < 4; q++) acc[j][n][q] = 0.0f;
#pragma unroll 1
                for (int kc = 0; kc < 4; kc++) {
                    __syncthreads();
#pragma unroll
                    for (int i = 0; i < 8; i++) {
                        int u = t + i * 256;
                        int tile = u >> 10, r = (u >> 3) & 127, q = u & 7;
                        const __half* src = (tile ? S1b : S1a)
                            + (size_t)(np * 128 + r) * 256 + kc * 64 + q * 8;
                        CP16(smb + FG_BS + tile * 16384 + SWZ(r * 128 + q * 16), src);
                    }
                    CPC(); cp_wait<0>(); __syncthreads();
#pragma unroll
                    for (int kk = 0; kk < 4; kk++) {
                        uint32_t a[4][4], bf[4][2];
#pragma unroll
                        for (int j = 0; j < 4; j++)
                            ldm4(a[j], smb + FG_VT + kc * 16384 +
                                 SWZ((wm * 16 + j * 32 + arow) * 128 + kk * 32 + acolb));
#pragma unroll
                        for (int nb = 0; nb < 2; nb++) {
                            uint32_t r4[4];
                            ldm4(r4, smb + FG_BS +
                                 SWZ((wn * 32 + nb * 16 + brow) * 128 + kk * 32 + bcolb));
                            bf[nb * 2][0] = r4[0]; bf[nb * 2][1] = r4[1];
                            bf[nb * 2 + 1][0] = r4[2]; bf[nb * 2 + 1][1] = r4[3];
                        }
#pragma unroll
                        for (int j = 0; j < 4; j++)
#pragma unroll
                            for (int n = 0; n < 4; n++)
                                mma16816(acc[j][n], a[j], bf[n]);
#pragma unroll
                        for (int nb = 0; nb < 2; nb++) {
                            uint32_t r4[4];
                            ldm4(r4, smb + FG_BS + 16384 +
                                 SWZ((wn * 32 + nb * 16 + brow) * 128 + kk * 32 + bcolb));
                            bf[nb * 2][0] = r4[0]; bf[nb * 2][1] = r4[1];
                            bf[nb * 2 + 1][0] = r4[2]; bf[nb * 2 + 1][1] = r4[3];
                        }
#pragma unroll
                        for (int j = 0; j < 4; j++)
#pragma unroll
                            for (int n = 0; n < 4; n++)
                                mma16816(acc[j][n], a[j], bf[n]);
                    }
                }
                __syncthreads();
                // epilogue: sample h, split, write AH/AL smem
                const uint32_t cbase = (uint32_t)(np * 128 + wn * 32 + t4 * 2);
#pragma unroll
                for (int j = 0; j < 2; j++)
#pragma unroll
                for (int hf = 0; hf < 2; hf++) {
                    int tr = wm * 16 + j * 32 + g + hf * 8;
                    uint32_t rowL = (uint32_t)(by * 64 + tr) * 256u;
#pragma unroll
                    for (int n = 0; n < 4; n++) {
                        uint32_t c = cbase + n * 8;
                        uint32_t iL = rowL + c, iH = iL + hlf;
                        float vL0 = acc[j][n][hf * 2 + 0], vL1 = acc[j][n][hf * 2 + 1];
                        float vH0 = acc[j + 2][n][hf * 2 + 0], vH1 = acc[j + 2][n][hf * 2 + 1];
                        float u0, u1, u2, u3;
                        tf_uniform2(rk0, rk1, iL, hlf, u0, u1);
                        tf_uniform2(rk0, rk1, iL + 1, hlf, u2, u3);
                        float2 wsL = *(const float2*)(ws + iL), wsH = *(const float2*)(ws + iH);
                        float2 cmL = *(const float2*)(cmod + iL), cmH = *(const float2*)(cmod + iH);
                        float a00 = (u0 < sigmoidf_(fmaf(vL0, wsL.x, cmL.x))) ? wsL.x : 0.0f;
                        float a01 = (u2 < sigmoidf_(fmaf(vL1, wsL.y, cmL.y))) ? wsL.y : 0.0f;
                        float a10 = (u1 < sigmoidf_(fmaf(vH0, wsH.x, cmH.x))) ? wsH.x : 0.0f;
                        float a11 = (u3 < sigmoidf_(fmaf(vH1, wsH.y, cmH.y))) ? wsH.y : 0.0f;
                        float h0, l0, h1, l1, h2, l2, h3, l3;
                        split2(a00, h0, l0); split2(a01, h1, l1);
                        split2(a10, h2, l2); split2(a11, h3, l3);
                        int chc = c >> 6;
                        uint32_t cb2 = (c & 63) * 2;
                        uint32_t offL = chc * 16384 + SWZ((uint32_t)tr * 128 + cb2);
                        uint32_t offH = chc * 16384 + SWZ((uint32_t)(tr + 64) * 128 + cb2);
                        *(uint32_t*)(sm + FG_AH + offL) = pkh(h0, h1);
                        *(uint32_t*)(sm + FG_AH + offH) = pkh(h2, h3);
                        *(uint32_t*)(sm + FG_AL + offL) = pkh(l0, l1);
                        *(uint32_t*)(sm + FG_AL + offH) = pkh(l2, l3);
                    }
                }
            }
        }
        __syncthreads();
        // ================= mode2: v-sample -> VT =================
        {
            const uint32_t rk0 = keys.a[s * 4 + 2], rk1 = keys.a[s * 4 + 3];
#pragma unroll 1
            for (int np = 0; np < 2; np++) {
                float acc[4][4][4];
#pragma unroll
                for (int j = 0; j < 4; j++)
#pragma unroll
                    for (int n = 0; n < 4; n++)
#pragma unroll
                        for (int q = 0; q < 4; q++) acc[j][n][q] = 0.0f;
#pragma unroll 1
                for (int kc = 0; kc < 4; kc++) {
                    __syncthreads();
#pragma unroll
                    for (int i = 0; i < 8; i++) {
                        int u = t + i * 256;
                        int tile = u >> 10, r = (u >> 3) & 127, q = u & 7;
                        const __half* src = (tile ? S2b : S2a)
                            + (size_t)(np * 128 + r) * 256 + kc * 64 + q * 8;
                        CP16(smb + FG_BS + tile * 16384 + SWZ(r * 128 + q * 16), src);
                    }
                    CPC(); cp_wait<0>(); __syncthreads();
#pragma unroll
                    for (int kk = 0; kk < 4; kk++) {
                        uint32_t a[4][4], bf[4][2];
#pragma unroll
                        for (int j = 0; j < 4; j++)
                            ldm4(a[j], smb + FG_AH + kc * 16384 +
                                 SWZ((wm * 16 + j * 32 + arow) * 128 + kk * 32 + acolb));
#pragma unroll
                        for (int nb = 0; nb < 2; nb++) {
                            uint32_t r4[4];
                            ldm4(r4, smb + FG_BS +
                                 SWZ((wn * 32 + nb * 16 + brow) * 128 + kk * 32 + bcolb));
                            bf[nb * 2][0] = r4[0]; bf[nb * 2][1] = r4[1];
                            bf[nb * 2 + 1][0] = r4[2]; bf[nb * 2 + 1][1] = r4[3];
                        }
#pragma unroll
                        for (int j = 0; j < 4; j++)
#pragma unroll
                            for (int n = 0; n < 4; n++)
                                mma16816(acc[j][n], a[j], bf[n]);
#pragma unroll
                        for (int nb = 0; nb < 2; nb++) {
                            uint32_t r4[4];
                            ldm4(r4, smb + FG_BS + 16384 +
                                 SWZ((wn * 32 + nb * 16 + brow) * 128 + kk * 32 + bcolb));
                            bf[nb * 2][0] = r4[0]; bf[nb * 2][1] = r4[1];
                            bf[nb * 2 + 1][0] = r4[2]; bf[nb * 2 + 1][1] = r4[3];
                        }
#pragma unroll
                        for (int j = 0; j < 4; j++)
#pragma unroll
                            for (int n = 0; n < 4; n++)
                                mma16816(acc[j][n], a[j], bf[n]);
                        // AL x S2a
#pragma unroll
                        for (int j = 0; j < 4; j++)
                            ldm4(a[j], smb + FG_AL + kc * 16384 +
                                 SWZ((wm * 16 + j * 32 + arow) * 128 + kk * 32 + acolb));
#pragma unroll
                        for (int nb = 0; nb < 2; nb++) {
                            uint32_t r4[4];
                            ldm4(r4, smb + FG_BS +
                                 SWZ((wn * 32 + nb * 16 + brow) * 128 + kk * 32 + bcolb));
                            bf[nb * 2][0] = r4[0]; bf[nb * 2][1] = r4[1];
                            bf[nb * 2 + 1][0] = r4[2]; bf[nb * 2 + 1][1] = r4[3];
                        }
#pragma unroll
                        for (int j = 0; j < 4; j++)
#pragma unroll
                            for (int n = 0; n < 4; n++)
                                mma16816(acc[j][n], a[j], bf[n]);
                    }
                }
                __syncthreads();
                // epilogue: sample v, write VT smem
                const uint32_t cbase = (uint32_t)(np * 128 + wn * 32 + t4 * 2);
#pragma unroll
                for (int j = 0; j < 2; j++)
#pragma unroll
                for (int hf = 0; hf < 2; hf++) {
                    int tr = wm * 16 + j * 32 + g + hf * 8;
                    uint32_t rowL = (uint32_t)(by * 64 + tr) * 256u;
#pragma unroll
                    for (int n = 0; n < 4; n++) {
                        uint32_t c = cbase + n * 8;
                        uint32_t iL = rowL + c, iH = iL + hlf;
                        float vL0 = acc[j][n][hf * 2 + 0], vL1 = acc[j][n][hf * 2 + 1];
                        float vH0 = acc[j + 2][n][hf * 2 + 0], vH1 = acc[j + 2][n][hf * 2 + 1];
                        float u0, u1, u2, u3;
                        tf_uniform2(rk0, rk1, iL, hlf, u0, u1);
                        tf_uniform2(rk0, rk1, iL + 1, hlf, u2, u3);
                        float2 bmL = *(const float2*)(bmod + iL), bmH = *(const float2*)(bmod + iH);
                        float b00 = (u0 < sigmoidf_(vL0 + bmL.x)) ? 1.0f : 0.0f;
                        float b01 = (u2 < sigmoidf_(vL1 + bmL.y)) ? 1.0f : 0.0f;
                        float b10 = (u1 < sigmoidf_(vH0 + bmH.x)) ? 1.0f : 0.0f;
                        float b11 = (u3 < sigmoidf_(vH1 + bmH.y)) ? 1.0f : 0.0f;
                        int chc = c >> 6;
                        uint32_t cb2 = (c & 63) * 2;
                        uint32_t offL = chc * 16384 + SWZ((uint32_t)tr * 128 + cb2);
                        uint32_t offH = chc * 16384 + SWZ((uint32_t)(tr + 64) * 128 + cb2);
                        *(uint32_t*)(sm + FG_VT + offL) = pkh(b00, b01);
                        *(uint32_t*)(sm + FG_VT + offH) = pkh(b10, b11);
                    }
                }
            }
        }
        __syncthreads();
    }

    // ---- dump VT -> v16 ----
#pragma unroll
    for (int i = 0; i < 16; i++) {
        int u = t + i * 256;
        int kcc = u >> 10, r = (u >> 3) & 127, q = u & 7;
        int gr = (r < 64) ? (by * 64 + r) : (Mh + by * 64 + (r - 64));
        uint4 val = *(const uint4*)(sm + FG_VT + kcc * 16384 + SWZ(r * 128 + q * 16));
        *(uint4*)(v16 + (size_t)gr * 256 + kcc * 64 + q * 8) = val;
    }
}

// ---------------- mode3 GEMM (plain fp32 logits for free energy) ----------------
#define MG_SMEM 65536

__global__ void __launch_bounds__(256, 2) mma_gemm3(
    const __half* __restrict__ A0,
    const __half* __restrict__ B0, const __half* __restrict__ B1,
    float* __restrict__ outf, int Bn)
{
    extern __shared__ char sm[];
    const uint32_t smb = smem_u32(sm);
    const int t = threadIdx.x;
    const int lane = t & 31;
    const int wid = t >> 5;
    const int wm = wid & 1, wn = wid >> 1;
    const int bx = blockIdx.x, by = blockIdx.y;
    const int Mh = Bn >> 1;

    float acc[4][4][4];
#pragma unroll
    for (int j = 0; j < 4; j++)
#pragma unroll
        for (int n = 0; n < 4; n++)
#pragma unroll
            for (int q = 0; q < 4; q++) acc[j][n][q] = 0.0f;

    const int arow = lane & 15;
    const int acolb = (lane >> 4) * 16;
    const int brow = (lane & 7) + (lane >> 4) * 8;
    const int bcolb = ((lane >> 3) & 1) * 16;

    for (int chunk = 0; chunk < 4; chunk++) {
        const int kc = chunk * 64;
        if (chunk) __syncthreads();
#pragma unroll
        for (int i = 0; i < 12; i++) {
            int u = t + i * 256;
            int tile = u >> 10;
            int r = (u >> 3) & 127;
            int q = u & 7;
            if (tile < 1) {
                int gr = (r < 64) ? (by * 64 + r) : (Mh + by * 64 + (r - 64));
                CP16(smb + SWZ(r * 128 + q * 16), A0 + (size_t)gr * 256 + kc + q * 8);
            } else {
                int bt = tile - 1;
                const __half* src = ((bt == 0) ? B0 : B1) + (size_t)(bx * 128 + r) * 256 + kc + q * 8;
                CP16(smb + 32768 + bt * 16384 + SWZ(r * 128 + q * 16), src);
            }
        }
        CPC();
        cp_wait<0>();
        __syncthreads();
#pragma unroll
        for (int kk = 0; kk < 4; kk++) {
            uint32_t a[4][4], bf[4][2];
#pragma unroll
            for (int j = 0; j < 4; j++)
                ldm4(a[j], smb + SWZ((wm * 16 + j * 32 + arow) * 128 + kk * 32 + acolb));
#pragma unroll
            for (int nb = 0; nb < 2; nb++) {
                uint32_t r4[4];
                ldm4(r4, smb + 32768 + SWZ((wn * 32 + nb * 16 + brow) * 128 + kk * 32 + bcolb));
                bf[nb * 2][0] = r4[0]; bf[nb * 2][1] = r4[1];
                bf[nb * 2 + 1][0] = r4[2]; bf[nb * 2 + 1][1] = r4[3];
            }
#pragma unroll
            for (int j = 0; j < 4; j++)
#pragma unroll
                for (int n = 0; n < 4; n++)
                    mma16816(acc[j][n], a[j], bf[n]);
#pragma unroll
            for (int nb = 0; nb < 2; nb++) {
                uint32_t r4[4];
                ldm4(r4, smb + 49152 + SWZ((wn * 32 + nb * 16 + brow) * 128 + kk * 32 + bcolb));
                bf[nb * 2][0] = r4[0]; bf[nb * 2][1] = r4[1];
                bf[nb * 2 + 1][0] = r4[2]; bf[nb * 2 + 1][1] = r4[3];
            }
#pragma unroll
            for (int j = 0; j < 4; j++)
#pragma unroll
                for (int n = 0; n < 4; n++)
                    mma16816(acc[j][n], a[j], bf[n]);
        }
    }

    const int g = lane >> 2, t4 = lane & 3;
    const uint32_t cbase = (uint32_t)(bx * 128 + wn * 32 + t4 * 2);
#pragma unroll
    for (int j = 0; j < 2; j++)
#pragma unroll
    for (int hf = 0; hf < 2; hf++) {
        int tr = wm * 16 + j * 32 + g + hf * 8;
        uint32_t rowL = (uint32_t)(by * 64 + tr) * 256u;
#pragma unroll
        for (int n = 0; n < 4; n++) {
            uint32_t iL = rowL + cbase + n * 8;
            uint32_t iH = iL + (uint32_t)Mh * 256u;
            *(float2*)(outf + iL) = make_float2(acc[j][n][hf * 2 + 0], acc[j][n][hf * 2 + 1]);
            *(float2*)(outf + iH) = make_float2(acc[j + 2][n][hf * 2 + 0], acc[j + 2][n][hf * 2 + 1]);
        }
    }
}

// ---------------- free-energy reduce ----------------
template <int VB>
__global__ void __launch_bounds__(256) fe_reduce_kernel(
    const float* __restrict__ vw, const float* __restrict__ vf,
    const __half* __restrict__ vb,
    const float* __restrict__ bmod, const float* __restrict__ cmod,
    const float* __restrict__ ws, const float* __restrict__ Wsum,
    float sign, float* __restrict__ part, int partBase)
{
    __shared__ float sW[256];
    __shared__ float wres[8];
    int t = threadIdx.x;
    sW[t] = Wsum[t];
    __syncthreads();
    int warp = t >> 5, lane = t & 31;
    int r = blockIdx.x * 8 + warp;
    size_t base = (size_t)r * 256;
    float s2v = 0.0f, s2f = 0.0f, s1v = 0.0f, s1f = 0.0f;
#pragma unroll
    for (int jj = 0; jj < 8; jj++) {
        int c = jj * 32 + lane;
        float tt = vw[base + c];
        float w  = ws[base + c];
        float cm = cmod[base + c];
        float tv = tt * w;
        s2v += softplusf_(tv + cm);
        s2f += softplusf_(fmaf(sW[c], w, cm) - tv);
        float bm = bmod[base + c];
        float vv = VB ? __half2float(vb[base + c]) : vf[base + c];
        s1v = fmaf(vv, bm, s1v);
        s1f = fmaf(1.0f - vv, bm, s1f);
    }
#pragma unroll
    for (int o = 16; o > 0; o >>= 1) {
        s2v += __shfl_xor_sync(0xffffffffu, s2v, o);
        s2f += __shfl_xor_sync(0xffffffffu, s2f, o);
        s1v += __shfl_xor_sync(0xffffffffu, s1v, o);
        s1f += __shfl_xor_sync(0xffffffffu, s1f, o);
    }
    if (lane == 0) {
        float av = s1v + s2v;
        float af = s1f + s2f;
        float mx = fmaxf(av, af);
        wres[warp] = sign * (-(mx + log1pf(expf(-fabsf(av - af)))));
    }
    __syncthreads();
    if (t == 0) {
        float s = 0.0f;
#pragma unroll
        for (int w = 0; w < 8; w++) s += wres[w];
        part[partBase + blockIdx.x] = s;
    }
}

__global__ void __launch_bounds__(256) final_reduce_kernel(
    const float* __restrict__ part, int n, float invB, float* __restrict__ out)
{
    __shared__ float s[256];
    float acc = 0.0f;
    for (int i = threadIdx.x; i < n; i += 256) acc += part[i];
    s[threadIdx.x] = acc;
    __syncthreads();
    for (int o = 128; o > 0; o >>= 1) {
        if (threadIdx.x < o) s[threadIdx.x] += s[threadIdx.x + o];
        __syncthreads();
    }
    if (threadIdx.x == 0) out[0] = s[0] * invB;
}

// ---------------- host: JAX key chain ----------------
static inline void host_split2(uint32_t k0, uint32_t k1, uint32_t* ka, uint32_t* kb) {
    uint32_t a0 = 0, b0 = 2; tf2x32(k0, k1, a0, b0);
    uint32_t a1 = 1, b1 = 3; tf2x32(k0, k1, a1, b1);
    ka[0] = a0; ka[1] = a1; kb[0] = b0; kb[1] = b1;
}
static inline void host_split3(uint32_t k0, uint32_t k1,
                               uint32_t* kA, uint32_t* kB, uint32_t* kC) {
    uint32_t a0 = 0, b0 = 3; tf2x32(k0, k1, a0, b0);
    uint32_t a1 = 1, b1 = 4; tf2x32(k0, k1, a1, b1);
    uint32_t a2 = 2, b2 = 5; tf2x32(k0, k1, a2, b2);
    kA[0] = a0; kA[1] = a1;
    kB[0] = a2; kB[1] = b0;
    kC[0] = b1; kC[1] = b2;
}

extern "C" void kernel_launch(void* const* d_in, const int* in_sizes, int n_in,
                              void* d_out, int out_size)
{
    const float* v_data = (const float*)d_in[0];
    const float* cond   = (const float*)d_in[1];
    const float* W      = (const float*)d_in[2];
    const float* b      = (const float*)d_in[3];
    const float* c      = (const float*)d_in[4];
    const float* fc1w   = (const float*)d_in[5];
    const float* fc1b   = (const float*)d_in[6];
    const float* fc2w   = (const float*)d_in[7];
    const float* fc2b   = (const float*)d_in[8];

    int B = in_sizes[0] / 256;
    if (B > BMAX) B = BMAX;
    int n_noise = (int)((double)B * 0.1);

    cudaFuncSetAttribute(fused_gibbs, cudaFuncAttributeMaxDynamicSharedMemorySize, FG_SMEM);
    cudaFuncSetAttribute(mma_gemm3, cudaFuncAttributeMaxDynamicSharedMemorySize, MG_SMEM);

    float *p_x, *p_cond, *p_t, *p_Wsum, *p_part, *p_P, *p_pb;
    __half *p_v16, *p_vd16, *p_S1, *p_S2;
    cudaGetSymbolAddress((void**)&p_x,    g_x);
    cudaGetSymbolAddress((void**)&p_cond, g_cond);
    cudaGetSymbolAddress((void**)&p_t,    g_t);
    cudaGetSymbolAddress((void**)&p_Wsum, g_Wsum);
    cudaGetSymbolAddress((void**)&p_part, g_part);
    cudaGetSymbolAddress((void**)&p_P,    g_P);
    cudaGetSymbolAddress((void**)&p_pb,   g_pb);
    cudaGetSymbolAddress((void**)&p_v16,  g_v16);
    cudaGetSymbolAddress((void**)&p_vd16, g_vd16);
    cudaGetSymbolAddress((void**)&p_S1,   g_S1);
    cudaGetSymbolAddress((void**)&p_S2,   g_S2);
    float* p_bmod = p_cond;
    float* p_cmod = p_cond + (size_t)B * 256;
    float* p_ws   = p_cond + (size_t)2 * B * 256;
    __half* S1a = p_S1; __half* S1b = p_S1 + 65536;
    __half* S2a = p_S2; __half* S2b = p_S2 + 65536;

    uint32_t rng[2] = {0u, 42u};
    uint32_t kn[2];
    host_split2(rng[0], rng[1], rng, kn);
    GKeys keys;
    for (int s = 0; s < 5; s++) {
        uint32_t nk[2], k1s[2], k2s[2];
        host_split3(rng[0], rng[1], nk, k1s, k2s);
        rng[0] = nk[0]; rng[1] = nk[1];
        keys.a[s * 4 + 0] = k1s[0]; keys.a[s * 4 + 1] = k1s[1];
        keys.a[s * 4 + 2] = k2s[0]; keys.a[s * 4 + 3] = k2s[1];
    }

    prep_kernel<<<128, 256>>>(W, b, c, fc2w, fc2b);
    cond_fc1_kernel<<<B / 64, 256>>>(cond, fc1w, fc1b, p_x);
    dim3 g0(6, B / 128);
    sgemm0_kernel<<<g0, 256>>>(p_x, p_P, p_cond, p_pb, B);
    init_v_kernel<<<2048, 256>>>(v_data, p_v16, p_vd16, B, n_noise, kn[0], kn[1]);

    uint32_t hlf = (uint32_t)B * 128u;
    fused_gibbs<<<B / 128, 256, FG_SMEM>>>(p_ws, p_cmod, p_bmod,
                                           S1a, S1b, S2a, S2b,
                                           p_v16, B, keys, hlf);

    dim3 gmm(2, B / 128);
    mma_gemm3<<<gmm, 256, MG_SMEM>>>(p_vd16, S1a, S1b, p_t, B);
    fe_reduce_kernel<0><<<B / 8, 256>>>(p_t, v_data, nullptr, p_bmod, p_cmod, p_ws,
                                        p_Wsum, 1.0f, p_part, 0);
    mma_gemm3<<<gmm, 256, MG_SMEM>>>(p_v16, S1a, S1b, p_t, B);
    fe_reduce_kernel<1><<<B / 8, 256>>>(p_t, nullptr, p_v16, p_bmod, p_cmod, p_ws,
                                        p_Wsum, -1.0f, p_part, B / 8);

    final_reduce_kernel<<<1, 256>>>(p_part, 2 * (B / 8), 1.0f / (float)B, (float*)d_out);
}

// round 14
// speedup vs baseline: 1.3868x; 1.3868x over previous
#include <cuda_runtime.h>
#include <cuda_fp16.h>
#include <cstdint>
#include <cstddef>

#define BMAX 32768

__device__ float g_cond[3 * BMAX * 256];
__device__ float g_t[BMAX * 256];
__device__ float g_pb[768];
__device__ float g_Wsum[256];
__device__ float g_part[BMAX / 4];
__device__ __half g_xhi[BMAX * 64];
__device__ __half g_xlo[BMAX * 64];
__device__ __half g_Phi[768 * 64];
__device__ __half g_Plo[768 * 64];
__device__ __half g_v16[BMAX * 256];
__device__ __half g_vd16[BMAX * 256];
__device__ __half g_ahi[BMAX * 256];
__device__ __half g_alo[BMAX * 256];
__device__ __half g_S1[2][256 * 256];   // v@W:   S1[s][n*256+k] = split_s(W[k,n])
__device__ __half g_S2[2][256 * 256];   // a@W^T: S2[s][n*256+k] = split_s(W[n,k])

__host__ __device__ inline uint32_t rotl32(uint32_t v, int d) { return (v << d) | (v >> (32 - d)); }

__host__ __device__ inline void tf2x32(uint32_t k0, uint32_t k1, uint32_t& x0, uint32_t& x1) {
    uint32_t ks2 = k0 ^ k1 ^ 0x1BD11BDAu;
    x0 += k0; x1 += k1;
    x0 += x1; x1 = rotl32(x1, 13); x1 ^= x0;
    x0 += x1; x1 = rotl32(x1, 15); x1 ^= x0;
    x0 += x1; x1 = rotl32(x1, 26); x1 ^= x0;
    x0 += x1; x1 = rotl32(x1,  6); x1 ^= x0;
    x0 += k1;  x1 += ks2 + 1u;
    x0 += x1; x1 = rotl32(x1, 17); x1 ^= x0;
    x0 += x1; x1 = rotl32(x1, 29); x1 ^= x0;
    x0 += x1; x1 = rotl32(x1, 16); x1 ^= x0;
    x0 += x1; x1 = rotl32(x1, 24); x1 ^= x0;
    x0 += ks2; x1 += k0 + 2u;
    x0 += x1; x1 = rotl32(x1, 13); x1 ^= x0;
    x0 += x1; x1 = rotl32(x1, 15); x1 ^= x0;
    x0 += x1; x1 = rotl32(x1, 26); x1 ^= x0;
    x0 += x1; x1 = rotl32(x1,  6); x1 ^= x0;
    x0 += k0;  x1 += k1 + 3u;
    x0 += x1; x1 = rotl32(x1, 17); x1 ^= x0;
    x0 += x1; x1 = rotl32(x1, 29); x1 ^= x0;
    x0 += x1; x1 = rotl32(x1, 16); x1 ^= x0;
    x0 += x1; x1 = rotl32(x1, 24); x1 ^= x0;
    x0 += k1;  x1 += ks2 + 4u;
    x0 += x1; x1 = rotl32(x1, 13); x1 ^= x0;
    x0 += x1; x1 = rotl32(x1, 15); x1 ^= x0;
    x0 += x1; x1 = rotl32(x1, 26); x1 ^= x0;
    x0 += x1; x1 = rotl32(x1,  6); x1 ^= x0;
    x0 += ks2; x1 += k0 + 5u;
}

__device__ inline void tf_uniform2(uint32_t k0, uint32_t k1, uint32_t f, uint32_t half_,
                                   float& u0, float& u1) {
    uint32_t x0 = f, x1 = f + half_;
    tf2x32(k0, k1, x0, x1);
    u0 = __uint_as_float((x0 >> 9) | 0x3f800000u) - 1.0f;
    u1 = __uint_as_float((x1 >> 9) | 0x3f800000u) - 1.0f;
}

__device__ inline float sigmoidf_(float x) {
    float e = expf(-fabsf(x));
    float s = 1.0f / (1.0f + e);
    return (x >= 0.0f) ? s : (1.0f - s);
}
__device__ inline float softplusf_(float x) {
    return fmaxf(x, 0.0f) + log1pf(expf(-fabsf(x)));
}

// ---------------- smem / mma helpers ----------------
__device__ __forceinline__ uint32_t smem_u32(const void* p) {
    uint32_t a;
    asm("{ .reg .u64 t; cvta.to.shared.u64 t, %1; cvt.u32.u64 %0, t; }" : "=r"(a) : "l"(p));
    return a;
}
#define SWZ(o) ((o) ^ (((o) >> 3) & 0x70))

#define CP16(dst, src) \
    asm volatile("cp.async.cg.shared.global [%0], [%1], 16;" :: "r"(dst), "l"(src))
#define CPC() asm volatile("cp.async.commit_group;" ::: "memory")
template <int N> __device__ __forceinline__ void cp_wait() {
    asm volatile("cp.async.wait_group %0;" :: "n"(N) : "memory");
}

__device__ __forceinline__ void ldm4(uint32_t* r, uint32_t a) {
    asm volatile("ldmatrix.sync.aligned.m8n8.x4.shared.b16 {%0,%1,%2,%3}, [%4];"
        : "=r"(r[0]), "=r"(r[1]), "=r"(r[2]), "=r"(r[3]) : "r"(a));
}
__device__ __forceinline__ void mma16816(float* d, const uint32_t* a, const uint32_t* b) {
    asm volatile(
        "mma.sync.aligned.m16n8k16.row.col.f32.f16.f16.f32 "
        "{%0,%1,%2,%3}, {%4,%5,%6,%7}, {%8,%9}, {%0,%1,%2,%3};"
        : "+f"(d[0]), "+f"(d[1]), "+f"(d[2]), "+f"(d[3])
        : "r"(a[0]), "r"(a[1]), "r"(a[2]), "r"(a[3]), "r"(b[0]), "r"(b[1]));
}

__device__ __forceinline__ uint32_t pkh(float x, float y) {
    __half2 h = __floats2half2_rn(x, y);
    return *(uint32_t*)&h;
}
__device__ __forceinline__ void split2(float a, float& hi, float& lo) {
    hi = __half2float(__float2half_rn(a));
    lo = a - hi;
}

// ---------------- prep: fp16 splits of W and P, pb, Wsum ----------------
__global__ void __launch_bounds__(256) prep_kernel(
    const float* __restrict__ W, const float* __restrict__ b, const float* __restrict__ c,
    const float* __restrict__ fc2w, const float* __restrict__ fc2b)
{
    int idx = blockIdx.x * blockDim.x + threadIdx.x;
    int stride = gridDim.x * blockDim.x;
    for (int i = idx; i < 256 * 256; i += stride) {
        int n = i >> 8, k = i & 255;
        float w1 = W[k * 256 + n];
        float h1, l1; split2(w1, h1, l1);
        g_S1[0][i] = __float2half_rn(h1);
        g_S1[1][i] = __float2half_rn(l1);
        float w2 = W[n * 256 + k];
        float h2, l2; split2(w2, h2, l2);
        g_S2[0][i] = __float2half_rn(h2);
        g_S2[1][i] = __float2half_rn(l2);
    }
    for (int i = idx; i < 64 * 768; i += stride) {
        int k = i / 768, n = i % 768;
        float val;
        if (n < 256)      val = b[n] * fc2w[n * 64 + k] + fc2w[(256 + n) * 64 + k];
        else if (n < 512) { int j = n - 256; val = c[j] * fc2w[(512 + j) * 64 + k] + fc2w[(768 + j) * 64 + k]; }
        else              { int j = n - 512; val = fc2w[(1024 + j) * 64 + k]; }
        float h, l; split2(val, h, l);
        g_Phi[n * 64 + k] = __float2half_rn(h);
        g_Plo[n * 64 + k] = __float2half_rn(l);
    }
    for (int i = idx; i < 768; i += stride) {
        float val;
        if (i < 256)      val = b[i] * (1.0f + fc2b[i]) + fc2b[256 + i];
        else if (i < 512) { int j = i - 256; val = c[j] * (1.0f + fc2b[512 + j]) + fc2b[768 + j]; }
        else              { int j = i - 512; val = fc2b[1024 + j]; }
        g_pb[i] = val;
    }
    for (int i = idx; i < 256; i += stride) {
        float s = 0.0f;
        for (int rr = 0; rr < 256; rr++) s += W[rr * 256 + i];
        g_Wsum[i] = s;
    }
}

// ---------------- cond fc1: x = tanh(cond @ fc1_w.T + fc1_b) -> fp16 splits ----------------
__global__ void __launch_bounds__(256) cond_fc1_kernel(
    const float* __restrict__ cond, const float* __restrict__ fc1w,
    const float* __restrict__ fc1b, __half* __restrict__ xhi, __half* __restrict__ xlo)
{
    __shared__ float Cs[64][65];
    __shared__ float Ws[64][65];
    int t = threadIdx.x;
    int r0 = blockIdx.x * 64;
#pragma unroll
    for (int l = 0; l < 4; l++) {
        int id = t + l * 256;
        int j = id >> 4, k4 = (id & 15) << 2;
        float4 w = *(const float4*)(fc1w + j * 64 + k4);
        Ws[k4 + 0][j] = w.x; Ws[k4 + 1][j] = w.y; Ws[k4 + 2][j] = w.z; Ws[k4 + 3][j] = w.w;
    }
#pragma unroll
    for (int l = 0; l < 4; l++) {
        int id = t + l * 256;
        int i = id >> 4, k4 = (id & 15) << 2;
        float4 v = *(const float4*)(cond + (size_t)(r0 + i) * 64 + k4);
        Cs[i][k4 + 0] = v.x; Cs[i][k4 + 1] = v.y; Cs[i][k4 + 2] = v.z; Cs[i][k4 + 3] = v.w;
    }
    __syncthreads();
    int tx = t & 15, ty = t >> 4;
    float acc[4][4];
#pragma unroll
    for (int i = 0; i < 4; i++)
#pragma unroll
        for (int j = 0; j < 4; j++) acc[i][j] = 0.0f;
#pragma unroll 8
    for (int k = 0; k < 64; k++) {
        float a[4], bv[4];
#pragma unroll
        for (int i = 0; i < 4; i++) a[i] = Cs[ty * 4 + i][k];
#pragma unroll
        for (int j = 0; j < 4; j++) bv[j] = Ws[k][tx * 4 + j];
#pragma unroll
        for (int i = 0; i < 4; i++)
#pragma unroll
            for (int j = 0; j < 4; j++) acc[i][j] = fmaf(a[i], bv[j], acc[i][j]);
    }
#pragma unroll
    for (int i = 0; i < 4; i++) {
        int r = r0 + ty * 4 + i;
#pragma unroll
        for (int j = 0; j < 4; j++) {
            int jj = tx * 4 + j;
            float val = tanhf(acc[i][j] + fc1b[jj]);
            float h, l; split2(val, h, l);
            xhi[(size_t)r * 64 + jj] = __float2half_rn(h);
            xlo[(size_t)r * 64 + jj] = __float2half_rn(l);
        }
    }
}

// ---------------- cond-param GEMM on tensor cores (K=64, N=768) ----------------
// streams: xhi*Phi, xhi*Plo, xlo*Phi. Epilogue: +pb, tanh-scale for c>=512.
#define G0_SMEM 65536

__global__ void __launch_bounds__(256, 2) mma_gemm0(
    const __half* __restrict__ Xhi, const __half* __restrict__ Xlo,
    const __half* __restrict__ Phi, const __half* __restrict__ Plo,
    const float* __restrict__ pb, float* __restrict__ out, int Bn)
{
    extern __shared__ char sm[];
    const uint32_t smb = smem_u32(sm);
    const int t = threadIdx.x;
    const int lane = t & 31;
    const int wid = t >> 5;
    const int wm = wid & 1, wn = wid >> 1;
    const int bx = blockIdx.x, by = blockIdx.y;

    // stage: Ahi@0, Alo@16384, Bhi@32768, Blo@49152 (each 128 rows x 64 fp16)
#pragma unroll
    for (int i = 0; i < 16; i++) {
        int u = t + i * 256;
        int tile = u >> 10, r = (u >> 3) & 127, q = u & 7;
        const __half* src;
        if (tile == 0)      src = Xhi + (size_t)(by * 128 + r) * 64 + q * 8;
        else if (tile == 1) src = Xlo + (size_t)(by * 128 + r) * 64 + q * 8;
        else if (tile == 2) src = Phi + (size_t)(bx * 128 + r) * 64 + q * 8;
        else                src = Plo + (size_t)(bx * 128 + r) * 64 + q * 8;
        CP16(smb + tile * 16384 + SWZ(r * 128 + q * 16), src);
    }
    CPC(); cp_wait<0>(); __syncthreads();

    float acc[4][4][4];
#pragma unroll
    for (int j = 0; j < 4; j++)
#pragma unroll
        for (int n = 0; n < 4; n++)
#pragma unroll
            for (int q = 0; q < 4; q++) acc[j][n][q] = 0.0f;

    const int arow = lane & 15;
    const int acolb = (lane >> 4) * 16;
    const int brow = (lane & 7) + (lane >> 4) * 8;
    const int bcolb = ((lane >> 3) & 1) * 16;

#pragma unroll
    for (int kk = 0; kk < 4; kk++) {
        uint32_t a[4][4], bf[4][2];
#pragma unroll
        for (int j = 0; j < 4; j++)
            ldm4(a[j], smb + SWZ((wm * 16 + j * 32 + arow) * 128 + kk * 32 + acolb));
#pragma unroll
        for (int nb = 0; nb < 2; nb++) {
            uint32_t r4[4];
            ldm4(r4, smb + 32768 + SWZ((wn * 32 + nb * 16 + brow) * 128 + kk * 32 + bcolb));
            bf[nb * 2][0] = r4[0]; bf[nb * 2][1] = r4[1];
            bf[nb * 2 + 1][0] = r4[2]; bf[nb * 2 + 1][1] = r4[3];
        }
#pragma unroll
        for (int j = 0; j < 4; j++)
#pragma unroll
            for (int n = 0; n < 4; n++)
                mma16816(acc[j][n], a[j], bf[n]);
#pragma unroll
        for (int nb = 0; nb < 2; nb++) {
            uint32_t r4[4];
            ldm4(r4, smb + 49152 + SWZ((wn * 32 + nb * 16 + brow) * 128 + kk * 32 + bcolb));
            bf[nb * 2][0] = r4[0]; bf[nb * 2][1] = r4[1];
            bf[nb * 2 + 1][0] = r4[2]; bf[nb * 2 + 1][1] = r4[3];
        }
#pragma unroll
        for (int j = 0; j < 4; j++)
#pragma unroll
            for (int n = 0; n < 4; n++)
                mma16816(acc[j][n], a[j], bf[n]);
        // xlo * Phi
#pragma unroll
        for (int j = 0; j < 4; j++)
            ldm4(a[j], smb + 16384 + SWZ((wm * 16 + j * 32 + arow) * 128 + kk * 32 + acolb));
#pragma unroll
        for (int nb = 0; nb < 2; nb++) {
            uint32_t r4[4];
            ldm4(r4, smb + 32768 + SWZ((wn * 32 + nb * 16 + brow) * 128 + kk * 32 + bcolb));
            bf[nb * 2][0] = r4[0]; bf[nb * 2][1] = r4[1];
            bf[nb * 2 + 1][0] = r4[2]; bf[nb * 2 + 1][1] = r4[3];
        }
#pragma unroll
        for (int j = 0; j < 4; j++)
#pragma unroll
            for (int n = 0; n < 4; n++)
                mma16816(acc[j][n], a[j], bf[n]);
    }

    const int g = lane >> 2, t4 = lane & 3;
#pragma unroll
    for (int j = 0; j < 4; j++)
#pragma unroll
    for (int hf = 0; hf < 2; hf++) {
        int r = by * 128 + wm * 16 + j * 32 + g + hf * 8;
#pragma unroll
        for (int n = 0; n < 4; n++) {
            int c = bx * 128 + wn * 32 + t4 * 2 + n * 8;
            float v0 = acc[j][n][hf * 2 + 0] + pb[c];
            float v1 = acc[j][n][hf * 2 + 1] + pb[c + 1];
            if (c >= 512) {
                v0 = 1.0f + 0.05f * tanhf(v0);
                v1 = 1.0f + 0.05f * tanhf(v1);
            }
            size_t o = (size_t)(c >> 8) * Bn * 256 + (size_t)r * 256 + (c & 255);
            out[o] = v0;
            out[o + 1] = v1;
        }
    }
}

// ---------------- init: vd16 = fp16(v_data); v16 = copy (vectorized) + noise ----------------
__global__ void __launch_bounds__(256) init_v_kernel(
    const float* __restrict__ vdata, __half* __restrict__ v16,
    __half* __restrict__ vd16, int B, int n_noise, uint32_t k0, uint32_t k1)
{
    int total4 = B * 64;
    for (int i4 = blockIdx.x * blockDim.x + threadIdx.x; i4 < total4;
         i4 += gridDim.x * blockDim.x) {
        float4 vd = ((const float4*)vdata)[i4];
        uint2 p;
        p.x = pkh(vd.x, vd.y);
        p.y = pkh(vd.z, vd.w);
        ((uint2*)vd16)[i4] = p;
        if ((i4 >> 6) >= n_noise) ((uint2*)v16)[i4] = p;
    }
    uint32_t half_ = (uint32_t)(n_noise * 128);
    int nPair2 = n_noise * 64;   // pairs of adjacent elements in [0, half_)
    for (int f2 = blockIdx.x * blockDim.x + threadIdx.x; f2 < nPair2;
         f2 += gridDim.x * blockDim.x) {
        uint32_t f = (uint32_t)f2 * 2u;
        float u0, u1, u2, u3;
        tf_uniform2(k0, k1, f, half_, u0, u1);
        tf_uniform2(k0, k1, f + 1, half_, u2, u3);
        *(uint32_t*)(v16 + f) = pkh((u0 < 0.5f) ? 1.0f : 0.0f, (u2 < 0.5f) ? 1.0f : 0.0f);
        *(uint32_t*)(v16 + f + half_) = pkh((u1 < 0.5f) ? 1.0f : 0.0f, (u3 < 0.5f) ? 1.0f : 0.0f);
    }
}

// ---------------- fp16 mma.sync GEMM, chunk-staged (M=128 split rows, N=128) ----------------
// (identical to R12 885us kernel)
#define MG_SMEM 65536

template <int MODE>
__global__ void __launch_bounds__(256, 2) mma_gemm(
    const __half* __restrict__ A0, const __half* __restrict__ A1,
    const __half* __restrict__ B0, const __half* __restrict__ B1,
    const float* __restrict__ e0, const float* __restrict__ e1,
    float* __restrict__ outf,
    __half* __restrict__ o0, __half* __restrict__ o1,
    int Bn, uint32_t rk0, uint32_t rk1, uint32_t hlf)
{
    extern __shared__ char sm[];
    const uint32_t smb = smem_u32(sm);
    const int t = threadIdx.x;
    const int lane = t & 31;
    const int wid = t >> 5;
    const int wm = wid & 1, wn = wid >> 1;
    const int bx = blockIdx.x, by = blockIdx.y;
    const int Mh = Bn >> 1;
    constexpr int NA = (MODE == 2) ? 2 : 1;
    constexpr int NU = (NA + 2) * 4;

    float acc[4][4][4];
#pragma unroll
    for (int j = 0; j < 4; j++)
#pragma unroll
        for (int n = 0; n < 4; n++)
#pragma unroll
            for (int q = 0; q < 4; q++) acc[j][n][q] = 0.0f;

    const int arow = lane & 15;
    const int acolb = (lane >> 4) * 16;
    const int brow = (lane & 7) + (lane >> 4) * 8;
    const int bcolb = ((lane >> 3) & 1) * 16;

    for (int chunk = 0; chunk < 4; chunk++) {
        const int kc = chunk * 64;
        if (chunk) __syncthreads();
#pragma unroll
        for (int i = 0; i < NU; i++) {
            int u = t + i * 256;
            int tile = u >> 10;
            int r = (u >> 3) & 127;
            int q = u & 7;
            if (tile < NA) {
                int gr = (r < 64) ? (by * 64 + r) : (Mh + by * 64 + (r - 64));
                const __half* src = ((tile == 0) ? A0 : A1) + (size_t)gr * 256 + kc + q * 8;
                CP16(smb + tile * 16384 + SWZ(r * 128 + q * 16), src);
            } else {
                int bt = tile - NA;
                const __half* src = ((bt == 0) ? B0 : B1) + (size_t)(bx * 128 + r) * 256 + kc + q * 8;
                CP16(smb + 32768 + bt * 16384 + SWZ(r * 128 + q * 16), src);
            }
        }
        CPC();
        cp_wait<0>();
        __syncthreads();

#pragma unroll
        for (int kk = 0; kk < 4; kk++) {
            uint32_t a[4][4];
            uint32_t bf[4][2];
#pragma unroll
            for (int j = 0; j < 4; j++)
                ldm4(a[j], smb + SWZ((wm * 16 + j * 32 + arow) * 128 + kk * 32 + acolb));
#pragma unroll
            for (int nb = 0; nb < 2; nb++) {
                uint32_t r4[4];
                ldm4(r4, smb + 32768 + SWZ((wn * 32 + nb * 16 + brow) * 128 + kk * 32 + bcolb));
                bf[nb * 2][0] = r4[0]; bf[nb * 2][1] = r4[1];
                bf[nb * 2 + 1][0] = r4[2]; bf[nb * 2 + 1][1] = r4[3];
            }
#pragma unroll
            for (int j = 0; j < 4; j++)
#pragma unroll
                for (int n = 0; n < 4; n++)
                    mma16816(acc[j][n], a[j], bf[n]);
#pragma unroll
            for (int nb = 0; nb < 2; nb++) {
                uint32_t r4[4];
                ldm4(r4, smb + 49152 + SWZ((wn * 32 + nb * 16 + brow) * 128 + kk * 32 + bcolb));
                bf[nb * 2][0] = r4[0]; bf[nb * 2][1] = r4[1];
                bf[nb * 2 + 1][0] = r4[2]; bf[nb * 2 + 1][1] = r4[3];
            }
#pragma unroll
            for (int j = 0; j < 4; j++)
#pragma unroll
                for (int n = 0; n < 4; n++)
                    mma16816(acc[j][n], a[j], bf[n]);
            if (MODE == 2) {
#pragma unroll
                for (int j = 0; j < 4; j++)
                    ldm4(a[j], smb + 16384 + SWZ((wm * 16 + j * 32 + arow) * 128 + kk * 32 + acolb));
#pragma unroll
                for (int nb = 0; nb < 2; nb++) {
                    uint32_t r4[4];
                    ldm4(r4, smb + 32768 + SWZ((wn * 32 + nb * 16 + brow) * 128 + kk * 32 + bcolb));
                    bf[nb * 2][0] = r4[0]; bf[nb * 2][1] = r4[1];
                    bf[nb * 2 + 1][0] = r4[2]; bf[nb * 2 + 1][1] = r4[3];
                }
#pragma unroll
                for (int j = 0; j < 4; j++)
#pragma unroll
                    for (int n = 0; n < 4; n++)
                        mma16816(acc[j][n], a[j], bf[n]);
            }
        }
    }

    const int g = lane >> 2, t4 = lane & 3;
    const uint32_t cbase = (uint32_t)(bx * 128 + wn * 32 + t4 * 2);
#pragma unroll
    for (int j = 0; j < 2; j++)
#pragma unroll
    for (int hf = 0; hf < 2; hf++) {
        int tr = wm * 16 + j * 32 + g + hf * 8;
        uint32_t rowL = (uint32_t)(by * 64 + tr) * 256u;
#pragma unroll
        for (int n = 0; n < 4; n++) {
            uint32_t iL = rowL + cbase + n * 8;
            uint32_t iH = iL + hlf;
            float vL0 = acc[j][n][hf * 2 + 0], vL1 = acc[j][n][hf * 2 + 1];
            float vH0 = acc[j + 2][n][hf * 2 + 0], vH1 = acc[j + 2][n][hf * 2 + 1];
            if (MODE == 3) {
                *(float2*)(outf + iL) = make_float2(vL0, vL1);
                *(float2*)(outf + iH) = make_float2(vH0, vH1);
            } else {
                float u0, u1, u2, u3;
                tf_uniform2(rk0, rk1, iL, hlf, u0, u1);
                tf_uniform2(rk0, rk1, iL + 1, hlf, u2, u3);
                if (MODE == 1) {
                    float2 wsL = *(const float2*)(e0 + iL), wsH = *(const float2*)(e0 + iH);
                    float2 cmL = *(const float2*)(e1 + iL), cmH = *(const float2*)(e1 + iH);
                    float a00 = (u0 < sigmoidf_(fmaf(vL0, wsL.x, cmL.x))) ? wsL.x : 0.0f;
                    float a01 = (u2 < sigmoidf_(fmaf(vL1, wsL.y, cmL.y))) ? wsL.y : 0.0f;
                    float a10 = (u1 < sigmoidf_(fmaf(vH0, wsH.x, cmH.x))) ? wsH.x : 0.0f;
                    float a11 = (u3 < sigmoidf_(fmaf(vH1, wsH.y, cmH.y))) ? wsH.y : 0.0f;
                    float h0, l0, h1, l1, h2, l2, h3, l3;
                    split2(a00, h0, l0); split2(a01, h1, l1);
                    split2(a10, h2, l2); split2(a11, h3, l3);
                    *(uint32_t*)(o0 + iL) = pkh(h0, h1); *(uint32_t*)(o0 + iH) = pkh(h2, h3);
                    *(uint32_t*)(o1 + iL) = pkh(l0, l1); *(uint32_t*)(o1 + iH) = pkh(l2, l3);
                } else {
                    float2 bmL = *(const float2*)(e0 + iL), bmH = *(const float2*)(e0 + iH);
                    float b00 = (u0 < sigmoidf_(vL0 + bmL.x)) ? 1.0f : 0.0f;
                    float b01 = (u2 < sigmoidf_(vL1 + bmL.y)) ? 1.0f : 0.0f;
                    float b10 = (u1 < sigmoidf_(vH0 + bmH.x)) ? 1.0f : 0.0f;
                    float b11 = (u3 < sigmoidf_(vH1 + bmH.y)) ? 1.0f : 0.0f;
                    *(uint32_t*)(o0 + iL) = pkh(b00, b01);
                    *(uint32_t*)(o0 + iH) = pkh(b10, b11);
                }
            }
        }
    }
}

// ---------------- free-energy reduce ----------------
template <int VB>
__global__ void __launch_bounds__(256) fe_reduce_kernel(
    const float* __restrict__ vw, const float* __restrict__ vf,
    const __half* __restrict__ vb,
    const float* __restrict__ bmod, const float* __restrict__ cmod,
    const float* __restrict__ ws, const float* __restrict__ Wsum,
    float sign, float* __restrict__ part, int partBase)
{
    __shared__ float sW[256];
    __shared__ float wres[8];
    int t = threadIdx.x;
    sW[t] = Wsum[t];
    __syncthreads();
    int warp = t >> 5, lane = t & 31;
    int r = blockIdx.x * 8 + warp;
    size_t base = (size_t)r * 256;
    float s2v = 0.0f, s2f = 0.0f, s1v = 0.0f, s1f = 0.0f;
#pragma unroll
    for (int jj = 0; jj < 8; jj++) {
        int c = jj * 32 + lane;
        float tt = vw[base + c];
        float w  = ws[base + c];
        float cm = cmod[base + c];
        float tv = tt * w;
        s2v += softplusf_(tv + cm);
        s2f += softplusf_(fmaf(sW[c], w, cm) - tv);
        float bm = bmod[base + c];
        float vv = VB ? __half2float(vb[base + c]) : vf[base + c];
        s1v = fmaf(vv, bm, s1v);
        s1f = fmaf(1.0f - vv, bm, s1f);
    }
#pragma unroll
    for (int o = 16; o > 0; o >>= 1) {
        s2v += __shfl_xor_sync(0xffffffffu, s2v, o);
        s2f += __shfl_xor_sync(0xffffffffu, s2f, o);
        s1v += __shfl_xor_sync(0xffffffffu, s1v, o);
        s1f += __shfl_xor_sync(0xffffffffu, s1f, o);
    }
    if (lane == 0) {
        float av = s1v + s2v;
        float af = s1f + s2f;
        float mx = fmaxf(av, af);
        wres[warp] = sign * (-(mx + log1pf(expf(-fabsf(av - af)))));
    }
    __syncthreads();
    if (t == 0) {
        float s = 0.0f;
#pragma unroll
        for (int w = 0; w < 8; w++) s += wres[w];
        part[partBase + blockIdx.x] = s;
    }
}

__global__ void __launch_bounds__(256) final_reduce_kernel(
    const float* __restrict__ part, int n, float invB, float* __restrict__ out)
{
    __shared__ float s[256];
    float acc = 0.0f;
    for (int i = threadIdx.x; i < n; i += 256) acc += part[i];
    s[threadIdx.x] = acc;
    __syncthreads();
    for (int o = 128; o > 0; o >>= 1) {
        if (threadIdx.x < o) s[threadIdx.x] += s[threadIdx.x + o];
        __syncthreads();
    }
    if (threadIdx.x == 0) out[0] = s[0] * invB;
}

// ---------------- host: JAX key chain ----------------
static inline void host_split2(uint32_t k0, uint32_t k1, uint32_t* ka, uint32_t* kb) {
    uint32_t a0 = 0, b0 = 2; tf2x32(k0, k1, a0, b0);
    uint32_t a1 = 1, b1 = 3; tf2x32(k0, k1, a1, b1);
    ka[0] = a0; ka[1] = a1; kb[0] = b0; kb[1] = b1;
}
static inline void host_split3(uint32_t k0, uint32_t k1,
                               uint32_t* kA, uint32_t* kB, uint32_t* kC) {
    uint32_t a0 = 0, b0 = 3; tf2x32(k0, k1, a0, b0);
    uint32_t a1 = 1, b1 = 4; tf2x32(k0, k1, a1, b1);
    uint32_t a2 = 2, b2 = 5; tf2x32(k0, k1, a2, b2);
    kA[0] = a0; kA[1] = a1;
    kB[0] = a2; kB[1] = b0;
    kC[0] = b1; kC[1] = b2;
}

extern "C" void kernel_launch(void* const* d_in, const int* in_sizes, int n_in,
                              void* d_out, int out_size)
{
    const float* v_data = (const float*)d_in[0];
    const float* cond   = (const float*)d_in[1];
    const float* W      = (const float*)d_in[2];
    const float* b      = (const float*)d_in[3];
    const float* c      = (const float*)d_in[4];
    const float* fc1w   = (const float*)d_in[5];
    const float* fc1b   = (const float*)d_in[6];
    const float* fc2w   = (const float*)d_in[7];
    const float* fc2b   = (const float*)d_in[8];

    int B = in_sizes[0] / 256;
    if (B > BMAX) B = BMAX;
    int n_noise = (int)((double)B * 0.1);

    cudaFuncSetAttribute(mma_gemm0, cudaFuncAttributeMaxDynamicSharedMemorySize, G0_SMEM);
    cudaFuncSetAttribute(mma_gemm<1>, cudaFuncAttributeMaxDynamicSharedMemorySize, MG_SMEM);
    cudaFuncSetAttribute(mma_gemm<2>, cudaFuncAttributeMaxDynamicSharedMemorySize, MG_SMEM);
    cudaFuncSetAttribute(mma_gemm<3>, cudaFuncAttributeMaxDynamicSharedMemorySize, MG_SMEM);

    float *p_cond, *p_t, *p_Wsum, *p_part, *p_pb;
    __half *p_xhi, *p_xlo, *p_Phi, *p_Plo;
    __half *p_v16, *p_vd16, *p_ahi, *p_alo, *p_S1, *p_S2;
    cudaGetSymbolAddress((void**)&p_cond, g_cond);
    cudaGetSymbolAddress((void**)&p_t,    g_t);
    cudaGetSymbolAddress((void**)&p_Wsum, g_Wsum);
    cudaGetSymbolAddress((void**)&p_part, g_part);
    cudaGetSymbolAddress((void**)&p_pb,   g_pb);
    cudaGetSymbolAddress((void**)&p_xhi,  g_xhi);
    cudaGetSymbolAddress((void**)&p_xlo,  g_xlo);
    cudaGetSymbolAddress((void**)&p_Phi,  g_Phi);
    cudaGetSymbolAddress((void**)&p_Plo,  g_Plo);
    cudaGetSymbolAddress((void**)&p_v16,  g_v16);
    cudaGetSymbolAddress((void**)&p_vd16, g_vd16);
    cudaGetSymbolAddress((void**)&p_ahi,  g_ahi);
    cudaGetSymbolAddress((void**)&p_alo,  g_alo);
    cudaGetSymbolAddress((void**)&p_S1,   g_S1);
    cudaGetSymbolAddress((void**)&p_S2,   g_S2);
    float* p_bmod = p_cond;
    float* p_cmod = p_cond + (size_t)B * 256;
    float* p_ws   = p_cond + (size_t)2 * B * 256;
    __half* S1a = p_S1; __half* S1b = p_S1 + 65536;
    __half* S2a = p_S2; __half* S2b = p_S2 + 65536;

    uint32_t rng[2] = {0u, 42u};
    uint32_t kn[2];
    host_split2(rng[0], rng[1], rng, kn);
    uint32_t k1s[5][2], k2s[5][2];
    for (int s = 0; s < 5; s++) {
        uint32_t nk[2];
        host_split3(rng[0], rng[1], nk, k1s[s], k2s[s]);
        rng[0] = nk[0]; rng[1] = nk[1];
    }

    prep_kernel<<<128, 256>>>(W, b, c, fc2w, fc2b);
    cond_fc1_kernel<<<B / 64, 256>>>(cond, fc1w, fc1b, p_xhi, p_xlo);
    dim3 g0(6, B / 128);
    mma_gemm0<<<g0, 256, G0_SMEM>>>(p_xhi, p_xlo, p_Phi, p_Plo, p_pb, p_cond, B);
    init_v_kernel<<<2048, 256>>>(v_data, p_v16, p_vd16, B, n_noise, kn[0], kn[1]);

    uint32_t hlf = (uint32_t)B * 128u;
    dim3 gmm(2, B / 128);
    for (int s = 0; s < 5; s++) {
        mma_gemm<1><<<gmm, 256, MG_SMEM>>>(p_v16, nullptr,
                                           S1a, S1b,
                                           p_ws, p_cmod, nullptr,
                                           p_ahi, p_alo,
                                           B, k1s[s][0], k1s[s][1], hlf);
        mma_gemm<2><<<gmm, 256, MG_SMEM>>>(p_ahi, p_alo,
                                           S2a, S2b,
                                           p_bmod, nullptr, nullptr,
                                           p_v16, nullptr,
                                           B, k2s[s][0], k2s[s][1], hlf);
    }

    mma_gemm<3><<<gmm, 256, MG_SMEM>>>(p_vd16, nullptr,
                                       S1a, S1b,
                                       nullptr, nullptr, p_t,
                                       nullptr, nullptr,
                                       B, 0u, 0u, hlf);
    fe_reduce_kernel<0><<<B / 8, 256>>>(p_t, v_data, nullptr, p_bmod, p_cmod, p_ws,
                                        p_Wsum, 1.0f, p_part, 0);
    mma_gemm<3><<<gmm, 256, MG_SMEM>>>(p_v16, nullptr,
                                       S1a, S1b,
                                       nullptr, nullptr, p_t,
                                       nullptr, nullptr,
                                       B, 0u, 0u, hlf);
    fe_reduce_kernel<1><<<B / 8, 256>>>(p_t, nullptr, p_v16, p_bmod, p_cmod, p_ws,
                                        p_Wsum, -1.0f, p_part, B / 8);

    final_reduce_kernel<<<1, 256>>>(p_part, 2 * (B / 8), 1.0f / (float)B, (float*)d_out);
}